// round 5
// baseline (speedup 1.0000x reference)
#include <cuda_runtime.h>
#include <cuda_bf16.h>
#include <stdint.h>
#include <math.h>

// ---------- problem constants ----------
#define NROWS    131072           // 512 graphs * 256 nodes
#define INDIM    128
#define HIDN     128
#define D2       256              // K and N of both big GEMMs
#define MTILE    64               // rows per CTA
#define NCTA     (NROWS / MTILE)  // 2048
#define NTHREADS 256              // 8 warps: wm in {0,1}, wn in {0..3}; warp tile 32x64

// ---------- smem layout (bytes) ----------
#define SM_AHI   0
#define SM_ALO   32768
#define SM_EMB   65536            // 128 f32
#define SM_B1    66048            // 256 f32
#define SM_B2    67072            // 256 f32
#define SM_W3    68096            // 512 f32 ([256][2])
#define SM_RED   70144            // [4 wn][64 row][2] f32 = 2048B
#define SM_TOTAL 72192

// B fragments, fragment-major in global scratch:
// u32 index = ((((l*2+p)*16 + ks)*32 + lane)*64) + NT*2 + reg   (NT global 0..31)
__device__ uint32_t g_Bf[131072];   // 512KB

static __device__ __forceinline__ uint32_t pack_bf(__nv_bfloat16 a, __nv_bfloat16 b) {
    return ((uint32_t)__bfloat16_as_ushort(b) << 16) | (uint32_t)__bfloat16_as_ushort(a);
}
static __device__ __forceinline__ void split_bf(float v, __nv_bfloat16& hi, __nv_bfloat16& lo) {
    hi = __float2bfloat16(v);
    lo = __float2bfloat16(v - __bfloat162float(hi));
}

// ---------- prep: split W1/W2 into bf16 hi/lo fragments ----------
__global__ void prep_weights(const float* __restrict__ W1, const float* __restrict__ W2) {
    int i = blockIdx.x * blockDim.x + threadIdx.x;   // 0..131071
    int reg  = i & 1;
    int NT   = (i >> 1) & 31;
    int lane = (i >> 6) & 31;
    int ks   = (i >> 11) & 15;
    int p    = (i >> 15) & 1;
    int l    = i >> 16;
    const float* W = l ? W2 : W1;
    int k0 = ks * 16 + (lane & 3) * 2 + reg * 8;
    int n  = NT * 8 + (lane >> 2);
    float v0 = W[k0 * 256 + n];
    float v1 = W[(k0 + 1) * 256 + n];
    __nv_bfloat16 h0, l0, h1, l1;
    split_bf(v0, h0, l0);
    split_bf(v1, h1, l1);
    g_Bf[i] = (p == 0) ? pack_bf(h0, h1) : pack_bf(l0, l1);
}

// ---------- mma.sync wrapper ----------
static __device__ __forceinline__ void mma_bf16(float* d, const uint32_t* a,
                                                uint32_t b0, uint32_t b1) {
    asm volatile(
        "mma.sync.aligned.m16n8k16.row.col.f32.bf16.bf16.f32 "
        "{%0,%1,%2,%3}, {%4,%5,%6,%7}, {%8,%9}, {%0,%1,%2,%3};"
        : "+f"(d[0]), "+f"(d[1]), "+f"(d[2]), "+f"(d[3])
        : "r"(a[0]), "r"(a[1]), "r"(a[2]), "r"(a[3]), "r"(b0), "r"(b1));
}

// A smem byte offset for (row r, k) with conflict-free xor swizzle.
static __device__ __forceinline__ uint32_t offA(int r, int k) {
    uint32_t c = (uint32_t)(k & 15);
    uint32_t cp = (c + (uint32_t)((r & 4) << 1)) & 15u;
    return ((uint32_t)(k >> 4) << 11) + ((uint32_t)r << 5) + (cp << 1);
}

union Bfrag { uint4 q[4]; uint32_t b[16]; };

// ---------- one GEMM layer with register-double-buffered B prefetch ----------
static __device__ __forceinline__ void gemm_layer(const char* __restrict__ sm,
                                                  const uint32_t* __restrict__ gB,
                                                  int lane, int wm, int wn,
                                                  float (&acc)[2][8][4]) {
    const int g   = lane >> 2;
    const int tig = lane & 3;
    const int sw  = (g & 4) << 1;
    const int c0b = ((tig * 2 + sw) & 15) * 2;
    const int c2b = ((tig * 2 + 8 + sw) & 15) * 2;
    const int ro0 = g * 32;
    const int ro1 = (g + 8) * 32;
    const uint32_t lwoff = (uint32_t)lane * 64 + (uint32_t)wn * 16;

    #pragma unroll
    for (int mt = 0; mt < 2; mt++)
        #pragma unroll
        for (int nt = 0; nt < 8; nt++)
            #pragma unroll
            for (int c = 0; c < 4; c++)
                acc[mt][nt][c] = 0.f;

    Bfrag B0H, B0L, B1H, B1L;

    // prologue: load ks=0 into buffer 0
    {
        const uint4* p  = (const uint4*)(gB + lwoff);
        const uint4* pl = (const uint4*)(gB + 32768 + lwoff);
        #pragma unroll
        for (int i = 0; i < 4; i++) { B0H.q[i] = p[i]; B0L.q[i] = pl[i]; }
    }

    #pragma unroll 1
    for (int ks = 0; ks < 16; ks += 2) {
        // ---- prefetch ks+1 into buffer 1 ----
        {
            const uint4* p  = (const uint4*)(gB + (uint32_t)(ks + 1) * 2048 + lwoff);
            const uint4* pl = (const uint4*)(gB + 32768 + (uint32_t)(ks + 1) * 2048 + lwoff);
            #pragma unroll
            for (int i = 0; i < 4; i++) { B1H.q[i] = p[i]; B1L.q[i] = pl[i]; }
        }
        // ---- compute ks with buffer 0 ----
        {
            uint32_t aH[2][4], aL[2][4];
            const char* Ab = sm + ((uint32_t)ks << 11);
            #pragma unroll
            for (int mt = 0; mt < 2; mt++) {
                int mb = (wm * 32 + mt * 16) * 32;
                aH[mt][0] = *(const uint32_t*)(Ab + SM_AHI + mb + ro0 + c0b);
                aH[mt][1] = *(const uint32_t*)(Ab + SM_AHI + mb + ro1 + c0b);
                aH[mt][2] = *(const uint32_t*)(Ab + SM_AHI + mb + ro0 + c2b);
                aH[mt][3] = *(const uint32_t*)(Ab + SM_AHI + mb + ro1 + c2b);
                aL[mt][0] = *(const uint32_t*)(Ab + SM_ALO + mb + ro0 + c0b);
                aL[mt][1] = *(const uint32_t*)(Ab + SM_ALO + mb + ro1 + c0b);
                aL[mt][2] = *(const uint32_t*)(Ab + SM_ALO + mb + ro0 + c2b);
                aL[mt][3] = *(const uint32_t*)(Ab + SM_ALO + mb + ro1 + c2b);
            }
            #pragma unroll
            for (int mt = 0; mt < 2; mt++)
                #pragma unroll
                for (int nt = 0; nt < 8; nt++)
                    mma_bf16(acc[mt][nt], aH[mt], B0H.b[nt * 2], B0H.b[nt * 2 + 1]);
            #pragma unroll
            for (int mt = 0; mt < 2; mt++)
                #pragma unroll
                for (int nt = 0; nt < 8; nt++)
                    mma_bf16(acc[mt][nt], aH[mt], B0L.b[nt * 2], B0L.b[nt * 2 + 1]);
            #pragma unroll
            for (int mt = 0; mt < 2; mt++)
                #pragma unroll
                for (int nt = 0; nt < 8; nt++)
                    mma_bf16(acc[mt][nt], aL[mt], B0H.b[nt * 2], B0H.b[nt * 2 + 1]);
        }
        // ---- prefetch ks+2 into buffer 0 (clamped; redundant reload on last iter) ----
        {
            int ksn = (ks + 2 < 16) ? (ks + 2) : 15;
            const uint4* p  = (const uint4*)(gB + (uint32_t)ksn * 2048 + lwoff);
            const uint4* pl = (const uint4*)(gB + 32768 + (uint32_t)ksn * 2048 + lwoff);
            #pragma unroll
            for (int i = 0; i < 4; i++) { B0H.q[i] = p[i]; B0L.q[i] = pl[i]; }
        }
        // ---- compute ks+1 with buffer 1 ----
        {
            uint32_t aH[2][4], aL[2][4];
            const char* Ab = sm + ((uint32_t)(ks + 1) << 11);
            #pragma unroll
            for (int mt = 0; mt < 2; mt++) {
                int mb = (wm * 32 + mt * 16) * 32;
                aH[mt][0] = *(const uint32_t*)(Ab + SM_AHI + mb + ro0 + c0b);
                aH[mt][1] = *(const uint32_t*)(Ab + SM_AHI + mb + ro1 + c0b);
                aH[mt][2] = *(const uint32_t*)(Ab + SM_AHI + mb + ro0 + c2b);
                aH[mt][3] = *(const uint32_t*)(Ab + SM_AHI + mb + ro1 + c2b);
                aL[mt][0] = *(const uint32_t*)(Ab + SM_ALO + mb + ro0 + c0b);
                aL[mt][1] = *(const uint32_t*)(Ab + SM_ALO + mb + ro1 + c0b);
                aL[mt][2] = *(const uint32_t*)(Ab + SM_ALO + mb + ro0 + c2b);
                aL[mt][3] = *(const uint32_t*)(Ab + SM_ALO + mb + ro1 + c2b);
            }
            #pragma unroll
            for (int mt = 0; mt < 2; mt++)
                #pragma unroll
                for (int nt = 0; nt < 8; nt++)
                    mma_bf16(acc[mt][nt], aH[mt], B1H.b[nt * 2], B1H.b[nt * 2 + 1]);
            #pragma unroll
            for (int mt = 0; mt < 2; mt++)
                #pragma unroll
                for (int nt = 0; nt < 8; nt++)
                    mma_bf16(acc[mt][nt], aH[mt], B1L.b[nt * 2], B1L.b[nt * 2 + 1]);
            #pragma unroll
            for (int mt = 0; mt < 2; mt++)
                #pragma unroll
                for (int nt = 0; nt < 8; nt++)
                    mma_bf16(acc[mt][nt], aL[mt], B1H.b[nt * 2], B1H.b[nt * 2 + 1]);
        }
    }
}

// ---------- main fused kernel ----------
__global__ __launch_bounds__(NTHREADS, 1)
void fused_hmma_kernel(const float* __restrict__ last,
                       const float* __restrict__ h,
                       const float* __restrict__ We,
                       const float* __restrict__ be,
                       const float* __restrict__ b1,
                       const float* __restrict__ b2,
                       const float* __restrict__ W3,
                       const float* __restrict__ b3,
                       float* __restrict__ out) {
    extern __shared__ char sm[];
    const int tid  = threadIdx.x;
    const int lane = tid & 31;
    const int wid  = tid >> 5;
    const int wm   = wid >> 2;
    const int wn   = wid & 3;
    const int r0   = blockIdx.x * MTILE;
    const int grp  = r0 >> 8;

    float* sEmb = (float*)(sm + SM_EMB);
    float* sB1  = (float*)(sm + SM_B1);
    float* sB2  = (float*)(sm + SM_B2);
    float* sW3  = (float*)(sm + SM_W3);
    float* sRed = (float*)(sm + SM_RED);

    sB1[tid] = b1[tid];
    sB2[tid] = b2[tid];
    sW3[tid]       = W3[tid];
    sW3[tid + 256] = W3[tid + 256];

    if (tid < HIDN) {
        float acc = be[tid];
        const float* lrow = last + (size_t)grp * INDIM;
        #pragma unroll 4
        for (int k = 0; k < INDIM; k++)
            acc = fmaf(lrow[k], We[k * HIDN + tid], acc);
        sEmb[tid] = acc;
    }

    for (int idx = tid; idx < MTILE * 32; idx += NTHREADS) {
        int r = idx >> 5, kq = idx & 31, k = kq * 4;
        float4 v = *(const float4*)(h + (size_t)(r0 + r) * HIDN + k);
        __nv_bfloat16 h0, l0, h1, l1, h2, l2, h3, l3;
        split_bf(v.x, h0, l0); split_bf(v.y, h1, l1);
        split_bf(v.z, h2, l2); split_bf(v.w, h3, l3);
        uint32_t off = offA(r, k);
        *(uint2*)(sm + SM_AHI + off) = make_uint2(pack_bf(h0, h1), pack_bf(h2, h3));
        *(uint2*)(sm + SM_ALO + off) = make_uint2(pack_bf(l0, l1), pack_bf(l2, l3));
    }
    __syncthreads();

    for (int idx = tid; idx < MTILE * 32; idx += NTHREADS) {
        int r = idx >> 5, kq = idx & 31, k = 128 + kq * 4;
        float4 v = *(const float4*)(sEmb + kq * 4);
        __nv_bfloat16 h0, l0, h1, l1, h2, l2, h3, l3;
        split_bf(v.x, h0, l0); split_bf(v.y, h1, l1);
        split_bf(v.z, h2, l2); split_bf(v.w, h3, l3);
        uint32_t off = offA(r, k);
        *(uint2*)(sm + SM_AHI + off) = make_uint2(pack_bf(h0, h1), pack_bf(h2, h3));
        *(uint2*)(sm + SM_ALO + off) = make_uint2(pack_bf(l0, l1), pack_bf(l2, l3));
    }
    __syncthreads();

    const int g   = lane >> 2;
    const int tig = lane & 3;
    float acc[2][8][4];

    // ===== Layer 1 =====
    gemm_layer(sm, g_Bf, lane, wm, wn, acc);
    __syncthreads();

    #pragma unroll
    for (int mt = 0; mt < 2; mt++) {
        int rA = wm * 32 + mt * 16 + g;
        int rB = rA + 8;
        #pragma unroll
        for (int nt = 0; nt < 8; nt++) {
            int c0 = wn * 64 + nt * 8 + tig * 2;
            float t0 = tanhf(acc[mt][nt][0] + sB1[c0]);
            float t1 = tanhf(acc[mt][nt][1] + sB1[c0 + 1]);
            float t2 = tanhf(acc[mt][nt][2] + sB1[c0]);
            float t3 = tanhf(acc[mt][nt][3] + sB1[c0 + 1]);
            __nv_bfloat16 h0, l0, h1, l1;
            split_bf(t0, h0, l0); split_bf(t1, h1, l1);
            uint32_t oA = offA(rA, c0);
            *(uint32_t*)(sm + SM_AHI + oA) = pack_bf(h0, h1);
            *(uint32_t*)(sm + SM_ALO + oA) = pack_bf(l0, l1);
            split_bf(t2, h0, l0); split_bf(t3, h1, l1);
            uint32_t oB = offA(rB, c0);
            *(uint32_t*)(sm + SM_AHI + oB) = pack_bf(h0, h1);
            *(uint32_t*)(sm + SM_ALO + oB) = pack_bf(l0, l1);
        }
    }
    __syncthreads();

    // ===== Layer 2 =====
    gemm_layer(sm, g_Bf + 65536, lane, wm, wn, acc);

    float e[2][2][2];
    #pragma unroll
    for (int mt = 0; mt < 2; mt++)
        #pragma unroll
        for (int hh = 0; hh < 2; hh++) { e[mt][hh][0] = 0.f; e[mt][hh][1] = 0.f; }

    #pragma unroll
    for (int mt = 0; mt < 2; mt++)
        #pragma unroll
        for (int nt = 0; nt < 8; nt++) {
            int c0 = wn * 64 + nt * 8 + tig * 2;
            float o0 = tanhf(acc[mt][nt][0] + sB2[c0]);
            float o1 = tanhf(acc[mt][nt][1] + sB2[c0 + 1]);
            float o2 = tanhf(acc[mt][nt][2] + sB2[c0]);
            float o3 = tanhf(acc[mt][nt][3] + sB2[c0 + 1]);
            float w00 = sW3[2 * c0],     w01 = sW3[2 * c0 + 1];
            float w10 = sW3[2 * c0 + 2], w11 = sW3[2 * c0 + 3];
            e[mt][0][0] = fmaf(o0, w00, fmaf(o1, w10, e[mt][0][0]));
            e[mt][0][1] = fmaf(o0, w01, fmaf(o1, w11, e[mt][0][1]));
            e[mt][1][0] = fmaf(o2, w00, fmaf(o3, w10, e[mt][1][0]));
            e[mt][1][1] = fmaf(o2, w01, fmaf(o3, w11, e[mt][1][1]));
        }
    #pragma unroll
    for (int off = 1; off <= 2; off <<= 1)
        #pragma unroll
        for (int mt = 0; mt < 2; mt++)
            #pragma unroll
            for (int hh = 0; hh < 2; hh++) {
                e[mt][hh][0] += __shfl_xor_sync(0xffffffffu, e[mt][hh][0], off);
                e[mt][hh][1] += __shfl_xor_sync(0xffffffffu, e[mt][hh][1], off);
            }
    if (tig == 0) {
        #pragma unroll
        for (int mt = 0; mt < 2; mt++)
            #pragma unroll
            for (int hh = 0; hh < 2; hh++) {
                int row = wm * 32 + mt * 16 + g + hh * 8;
                sRed[wn * 128 + row * 2 + 0] = e[mt][hh][0];
                sRed[wn * 128 + row * 2 + 1] = e[mt][hh][1];
            }
    }
    __syncthreads();

    if (tid < 128) {
        int row  = tid >> 1;
        int comp = tid & 1;
        float s = sRed[row * 2 + comp] + sRed[128 + row * 2 + comp]
                + sRed[256 + row * 2 + comp] + sRed[384 + row * 2 + comp]
                + b3[comp];
        int rg = r0 + row;
        out[(size_t)(rg >> 8) * 512 + (size_t)(rg & 255) * 2 + comp] = s;
    }
}

extern "C" void kernel_launch(void* const* d_in, const int* in_sizes, int n_in,
                              void* d_out, int out_size) {
    const float* last = (const float*)d_in[0];
    const float* h    = (const float*)d_in[1];
    const float* We   = (const float*)d_in[2];
    const float* be   = (const float*)d_in[3];
    const float* W1   = (const float*)d_in[4];
    const float* b1   = (const float*)d_in[5];
    const float* W2   = (const float*)d_in[6];
    const float* b2   = (const float*)d_in[7];
    const float* W3   = (const float*)d_in[8];
    const float* b3   = (const float*)d_in[9];
    float* out = (float*)d_out;

    prep_weights<<<512, 256>>>(W1, W2);

    cudaFuncSetAttribute(fused_hmma_kernel,
                         cudaFuncAttributeMaxDynamicSharedMemorySize, SM_TOTAL);
    fused_hmma_kernel<<<NCTA, NTHREADS, SM_TOTAL>>>(last, h, We, be, b1, b2, W3, b3, out);
}